// round 13
// baseline (speedup 1.0000x reference)
#include <cuda_runtime.h>
#include <cstdint>
#include <cstddef>

// Butterfly transform: B=8192 rows, N=4096, 12 stages, increasing stride.
// R13 = R12 (best, 77.5us: quad packing, 192KB smem, persistent 148 CTAs,
// balanced 568x12 + 172x8 row tiles = 148x5, L2 prefetch, phase-scoped
// twiddle caches) + per-quad named-barrier pipelining:
//   Each full __syncthreads is split into 3 per-quad-slot producer/consumer
//   barriers: bar.arrive after producing slot q, bar.sync before consuming
//   it (count 1024 = 512 arrive + 512 sync). Warps flow across phase
//   boundaries instead of convoying, and the NEXT tile's phase-0 LDG+compute
//   overlaps the previous tile's phase-3 stores (slot-free barriers B3q,
//   primed before the loop). Dependency chain per slot:
//   ph0 write -> B0q -> ph1 rw -> B1q -> ph2 rw -> B2q -> ph3 read -> B3q
//   -> next tile ph0 write.  Barrier ids: B0=1+q, B1=4+q, B2=7+q, B3=10+q.

namespace {
constexpr int kN       = 4096;
constexpr int kBatch   = 8192;
constexpr int kThreads = 512;
constexpr int kTiles12 = 568;                               // 12-row tiles
constexpr int kTiles   = 740;                               // = 148 * 5
constexpr int kGrid    = 148;                               // persistent
constexpr int kSmem    = 3 * kN * (int)sizeof(float4);      // 196608 B
constexpr int kBarCnt  = 2 * kThreads;                      // arrive + sync
}

// float4-granule swizzle: XOR low-3 index bits with bits 3..5.
__device__ __forceinline__ int swz(int i) { return i ^ ((i >> 3) & 7); }

__device__ __forceinline__ void prefetch_l2(const void* p) {
    asm volatile("prefetch.global.L2 [%0];" :: "l"(p));
}

// Named-barrier producer/consumer ops (count = 1024: 512 arrive + 512 sync).
__device__ __forceinline__ void bar_arrive(int id) {
    asm volatile("bar.arrive %0, %1;" :: "r"(id), "r"(kBarCnt) : "memory");
}
__device__ __forceinline__ void bar_wait(int id) {
    asm volatile("bar.sync %0, %1;" :: "r"(id), "r"(kBarCnt) : "memory");
}

// Row offset and row count for tile index i.
__device__ __forceinline__ int tile_row0(int i) {
    return (i < kTiles12) ? 12 * i : 12 * kTiles12 + 8 * (i - kTiles12);
}
__device__ __forceinline__ int tile_rows(int i) {
    return (i < kTiles12) ? 12 : 8;
}

// One 2x2 butterfly applied to four rows packed in float4 lanes.
__device__ __forceinline__ void bfly(float4& x0, float4& x1, const float4 tm) {
    float4 y0, y1;
    y0.x = __fmaf_rn(tm.y, x1.x, tm.x * x0.x);
    y0.y = __fmaf_rn(tm.y, x1.y, tm.x * x0.y);
    y0.z = __fmaf_rn(tm.y, x1.z, tm.x * x0.z);
    y0.w = __fmaf_rn(tm.y, x1.w, tm.x * x0.w);
    y1.x = __fmaf_rn(tm.w, x1.x, tm.z * x0.x);
    y1.y = __fmaf_rn(tm.w, x1.y, tm.z * x0.y);
    y1.z = __fmaf_rn(tm.w, x1.z, tm.z * x0.z);
    y1.w = __fmaf_rn(tm.w, x1.w, tm.z * x0.w);
    x0 = y0;
    x1 = y1;
}

// Three in-register substages over 8 owned elements (local strides 1,2,4).
__device__ __forceinline__ void substages(float4 v[8], const float4 twr[3][4]) {
    bfly(v[0], v[1], twr[0][0]); bfly(v[2], v[3], twr[0][1]);
    bfly(v[4], v[5], twr[0][2]); bfly(v[6], v[7], twr[0][3]);
    bfly(v[0], v[2], twr[1][0]); bfly(v[1], v[3], twr[1][1]);
    bfly(v[4], v[6], twr[1][2]); bfly(v[5], v[7], twr[1][3]);
    bfly(v[0], v[4], twr[2][0]); bfly(v[1], v[5], twr[2][1]);
    bfly(v[2], v[6], twr[2][2]); bfly(v[3], v[7], twr[2][3]);
}

template <int NQ>
__device__ __forceinline__ void bf_body(const float* __restrict__ x,
                                        const float* __restrict__ tw,
                                        float* __restrict__ out,
                                        int row0, int nrow0, int nchunks,
                                        float4* buf) {
    const int t = threadIdx.x;
    const float4* tw4 = reinterpret_cast<const float4*>(tw);

    // ---------------- Phase 0: stages 0..2 (strides 1,2,4) ----------------
    {
        float4 twr[3][4];
        #pragma unroll
        for (int u = 0; u < 3; ++u)
            #pragma unroll
            for (int pm = 0; pm < 4; ++pm)
                twr[u][pm] = tw4[u * 2048 + 4 * t + pm];
        int off[8];
        #pragma unroll
        for (int m = 0; m < 8; ++m) off[m] = swz(8 * t + m);

        #pragma unroll
        for (int q = 0; q < NQ; ++q) {
            // Load elements 8t..8t+7 of rows 4q..4q+3 (2 LDG.128 per row),
            // and compute BEFORE waiting on the slot-free barrier: this work
            // overlaps the previous tile's phase 3.
            float4 r[4][2];
            #pragma unroll
            for (int j = 0; j < 4; ++j) {
                const float4* xr = reinterpret_cast<const float4*>(
                    x + (size_t)(row0 + 4 * q + j) * kN);
                r[j][0] = __ldg(xr + 2 * t);
                r[j][1] = __ldg(xr + 2 * t + 1);
            }
            float4 v[8];
            v[0] = make_float4(r[0][0].x, r[1][0].x, r[2][0].x, r[3][0].x);
            v[1] = make_float4(r[0][0].y, r[1][0].y, r[2][0].y, r[3][0].y);
            v[2] = make_float4(r[0][0].z, r[1][0].z, r[2][0].z, r[3][0].z);
            v[3] = make_float4(r[0][0].w, r[1][0].w, r[2][0].w, r[3][0].w);
            v[4] = make_float4(r[0][1].x, r[1][1].x, r[2][1].x, r[3][1].x);
            v[5] = make_float4(r[0][1].y, r[1][1].y, r[2][1].y, r[3][1].y);
            v[6] = make_float4(r[0][1].z, r[1][1].z, r[2][1].z, r[3][1].z);
            v[7] = make_float4(r[0][1].w, r[1][1].w, r[2][1].w, r[3][1].w);

            substages(v, twr);

            bar_wait(10 + q);            // slot q free (prev tile ph3 done)
            float4* B = buf + q * kN;
            #pragma unroll
            for (int m = 0; m < 8; ++m) B[off[m]] = v[m];
            bar_arrive(1 + q);           // slot q ready for phase 1
        }
    }

    // ------------- Phases 1,2: stages 3..8 (strides 8..256), smem ---------
    #pragma unroll
    for (int ph = 1; ph <= 2; ++ph) {
        const int ls = 3 * ph;          // 3 or 6
        const int s  = 1 << ls;         // 8 or 64
        const int b  = t >> ls;
        const int c  = t & (s - 1);

        float4 twr[3][4];
        #pragma unroll
        for (int u = 0; u < 3; ++u)
            #pragma unroll
            for (int pm = 0; pm < 4; ++pm)
                twr[u][pm] = tw4[(3 * ph + u) * 2048 + s * (4 * b + pm) + c];
        int off[8];
        #pragma unroll
        for (int m = 0; m < 8; ++m) off[m] = swz(b * 8 * s + c + s * m);

        // Prefetch the NEXT tile's data into L2 under phases 1-3 compute.
        if (ph == 1 && nrow0 >= 0) {
            const char* nb = reinterpret_cast<const char*>(
                x + (size_t)nrow0 * kN);
            #pragma unroll
            for (int k = 0; k < 3; ++k) {
                const int idx = t + 512 * k;
                if (idx < nchunks)
                    prefetch_l2(nb + (size_t)idx * 128);
            }
        }

        const int bin  = (ph == 1) ? 1 : 4;   // wait on
        const int bout = (ph == 1) ? 4 : 7;   // signal

        #pragma unroll
        for (int q = 0; q < NQ; ++q) {
            bar_wait(bin + q);           // slot q produced by prev phase
            float4* B = buf + q * kN;
            float4 v[8];
            #pragma unroll
            for (int m = 0; m < 8; ++m) v[m] = B[off[m]];

            substages(v, twr);

            #pragma unroll
            for (int m = 0; m < 8; ++m) B[off[m]] = v[m];
            bar_arrive(bout + q);
        }
    }

    // ------------- Phase 3: stages 9..11 (strides 512..2048) -> out -------
    {
        const int s = 512;  // b = 0, c = t
        float4 twr[3][4];
        #pragma unroll
        for (int u = 0; u < 3; ++u)
            #pragma unroll
            for (int pm = 0; pm < 4; ++pm)
                twr[u][pm] = tw4[(9 + u) * 2048 + s * pm + t];
        int off[8];
        #pragma unroll
        for (int m = 0; m < 8; ++m) off[m] = swz(t + s * m);

        #pragma unroll
        for (int q = 0; q < NQ; ++q) {
            bar_wait(7 + q);             // slot q done with phase 2
            float4* B = buf + q * kN;
            float4 v[8];
            #pragma unroll
            for (int m = 0; m < 8; ++m) v[m] = B[off[m]];
            bar_arrive(10 + q);          // smem reads done: slot q is free

            substages(v, twr);

            float* o0 = out + (size_t)(row0 + 4 * q) * kN;
            float* o1 = o0 + kN;
            float* o2 = o1 + kN;
            float* o3 = o2 + kN;
            #pragma unroll
            for (int m = 0; m < 8; ++m) {
                o0[t + s * m] = v[m].x;   // warp-contiguous 4B stores
                o1[t + s * m] = v[m].y;
                o2[t + s * m] = v[m].z;
                o3[t + s * m] = v[m].w;
            }
        }
    }
}

__global__ void __launch_bounds__(kThreads, 1)
butterfly_kernel(const float* __restrict__ x,
                 const float* __restrict__ tw,
                 float* __restrict__ out) {
    extern __shared__ float4 buf[];

    // Prime the slot-free barriers so tile 0's phase 0 doesn't block.
    bar_arrive(10);
    bar_arrive(11);
    bar_arrive(12);

    for (int tile = blockIdx.x; tile < kTiles; tile += kGrid) {
        const int row0  = tile_row0(tile);
        const int nt    = tile + kGrid;
        const int nrow0 = (nt < kTiles) ? tile_row0(nt) : -1;
        const int nchk  = (nt < kTiles) ? tile_rows(nt) * (kN * 4 / 128) : 0;

        if (tile < kTiles12) {
            bf_body<3>(x, tw, out, row0, nrow0, nchk, buf);   // 12-row tile
        } else {
            bf_body<2>(x, tw, out, row0, nrow0, nchk, buf);   // 8-row tile
        }
    }
}

extern "C" void kernel_launch(void* const* d_in, const int* in_sizes, int n_in,
                              void* d_out, int out_size) {
    const float* x  = (const float*)d_in[0];   // (8192, 4096) fp32
    const float* tw = (const float*)d_in[1];   // (1,1,12,2048,2,2) fp32
    float* out      = (float*)d_out;           // (8192, 4096) fp32

    cudaFuncSetAttribute(butterfly_kernel,
                         cudaFuncAttributeMaxDynamicSharedMemorySize, kSmem);
    butterfly_kernel<<<kGrid, kThreads, kSmem>>>(x, tw, out);
}

// round 14
// speedup vs baseline: 1.1437x; 1.1437x over previous
#include <cuda_runtime.h>
#include <cstdint>
#include <cstddef>

// Butterfly transform: B=8192 rows, N=4096, 12 stages, increasing stride.
// R14 = R12 (best, 77.5us: quad packing, 192KB smem, persistent 148 CTAs,
// balanced 568x12 + 172x8 row tiles = 148x5, L2 prefetch of next tile,
// phase-scoped twiddle caches) + two surgical changes:
//  1. HOIST each phase's twiddle LDGs above the preceding __syncthreads:
//     the ~250cyc L2 latency drains during barrier wait instead of gating
//     every warp's first butterfly after the barrier (~1-1.5K cyc/tile).
//     Old phase's cache is dead before the new loads -> no extra pressure.
//  2. Streaming hints: __ldcs on x (read once), __stcs on out (write once)
//     to preserve L2 for prefetched tiles + the shared twiddle array.

namespace {
constexpr int kN       = 4096;
constexpr int kBatch   = 8192;
constexpr int kThreads = 512;
constexpr int kTiles12 = 568;                               // 12-row tiles
constexpr int kTiles   = 740;                               // = 148 * 5
constexpr int kGrid    = 148;                               // persistent
constexpr int kSmem    = 3 * kN * (int)sizeof(float4);      // 196608 B
}

// float4-granule swizzle: XOR low-3 index bits with bits 3..5.
__device__ __forceinline__ int swz(int i) { return i ^ ((i >> 3) & 7); }

__device__ __forceinline__ void prefetch_l2(const void* p) {
    asm volatile("prefetch.global.L2 [%0];" :: "l"(p));
}

// Row offset and row count for tile index i.
__device__ __forceinline__ int tile_row0(int i) {
    return (i < kTiles12) ? 12 * i : 12 * kTiles12 + 8 * (i - kTiles12);
}
__device__ __forceinline__ int tile_rows(int i) {
    return (i < kTiles12) ? 12 : 8;
}

// One 2x2 butterfly applied to four rows packed in float4 lanes.
__device__ __forceinline__ void bfly(float4& x0, float4& x1, const float4 tm) {
    float4 y0, y1;
    y0.x = __fmaf_rn(tm.y, x1.x, tm.x * x0.x);
    y0.y = __fmaf_rn(tm.y, x1.y, tm.x * x0.y);
    y0.z = __fmaf_rn(tm.y, x1.z, tm.x * x0.z);
    y0.w = __fmaf_rn(tm.y, x1.w, tm.x * x0.w);
    y1.x = __fmaf_rn(tm.w, x1.x, tm.z * x0.x);
    y1.y = __fmaf_rn(tm.w, x1.y, tm.z * x0.y);
    y1.z = __fmaf_rn(tm.w, x1.z, tm.z * x0.z);
    y1.w = __fmaf_rn(tm.w, x1.w, tm.z * x0.w);
    x0 = y0;
    x1 = y1;
}

// Three in-register substages over 8 owned elements (local strides 1,2,4).
__device__ __forceinline__ void substages(float4 v[8], const float4 twr[3][4]) {
    bfly(v[0], v[1], twr[0][0]); bfly(v[2], v[3], twr[0][1]);
    bfly(v[4], v[5], twr[0][2]); bfly(v[6], v[7], twr[0][3]);
    bfly(v[0], v[2], twr[1][0]); bfly(v[1], v[3], twr[1][1]);
    bfly(v[4], v[6], twr[1][2]); bfly(v[5], v[7], twr[1][3]);
    bfly(v[0], v[4], twr[2][0]); bfly(v[1], v[5], twr[2][1]);
    bfly(v[2], v[6], twr[2][2]); bfly(v[3], v[7], twr[2][3]);
}

template <int NQ>
__device__ __forceinline__ void bf_body(const float* __restrict__ x,
                                        const float* __restrict__ tw,
                                        float* __restrict__ out,
                                        int row0, int nrow0, int nchunks,
                                        float4* buf) {
    const int t = threadIdx.x;
    const float4* tw4 = reinterpret_cast<const float4*>(tw);

    // ---------------- Phase 0: stages 0..2 (strides 1,2,4) ----------------
    {
        float4 twr[3][4];
        #pragma unroll
        for (int u = 0; u < 3; ++u)
            #pragma unroll
            for (int pm = 0; pm < 4; ++pm)
                twr[u][pm] = tw4[u * 2048 + 4 * t + pm];
        int off[8];
        #pragma unroll
        for (int m = 0; m < 8; ++m) off[m] = swz(8 * t + m);

        #pragma unroll
        for (int q = 0; q < NQ; ++q) {
            // Load elements 8t..8t+7 of rows 4q..4q+3 (2 LDG.128 per row).
            float4 r[4][2];
            #pragma unroll
            for (int j = 0; j < 4; ++j) {
                const float4* xr = reinterpret_cast<const float4*>(
                    x + (size_t)(row0 + 4 * q + j) * kN);
                r[j][0] = __ldcs(xr + 2 * t);       // read-once: evict-first
                r[j][1] = __ldcs(xr + 2 * t + 1);
            }
            // Transpose into row-packed float4 elements.
            float4 v[8];
            v[0] = make_float4(r[0][0].x, r[1][0].x, r[2][0].x, r[3][0].x);
            v[1] = make_float4(r[0][0].y, r[1][0].y, r[2][0].y, r[3][0].y);
            v[2] = make_float4(r[0][0].z, r[1][0].z, r[2][0].z, r[3][0].z);
            v[3] = make_float4(r[0][0].w, r[1][0].w, r[2][0].w, r[3][0].w);
            v[4] = make_float4(r[0][1].x, r[1][1].x, r[2][1].x, r[3][1].x);
            v[5] = make_float4(r[0][1].y, r[1][1].y, r[2][1].y, r[3][1].y);
            v[6] = make_float4(r[0][1].z, r[1][1].z, r[2][1].z, r[3][1].z);
            v[7] = make_float4(r[0][1].w, r[1][1].w, r[2][1].w, r[3][1].w);

            substages(v, twr);

            float4* B = buf + q * kN;
            #pragma unroll
            for (int m = 0; m < 8; ++m) B[off[m]] = v[m];
        }
    }

    // ---- HOISTED: phase-1 twiddle loads drain their L2 latency during
    // ---- the barrier instead of stalling every warp after it.
    const int b1 = t >> 3, c1 = t & 7;                    // s = 8
    float4 tw1[3][4];
    #pragma unroll
    for (int u = 0; u < 3; ++u)
        #pragma unroll
        for (int pm = 0; pm < 4; ++pm)
            tw1[u][pm] = tw4[(3 + u) * 2048 + 8 * (4 * b1 + pm) + c1];

    __syncthreads();

    // ------------- Phase 1: stages 3..5 (strides 8,16,32), smem -----------
    {
        int off[8];
        #pragma unroll
        for (int m = 0; m < 8; ++m) off[m] = swz(b1 * 64 + c1 + 8 * m);

        // Prefetch the NEXT tile's data into L2 under phases 1-3 compute.
        if (nrow0 >= 0) {
            const char* nb = reinterpret_cast<const char*>(
                x + (size_t)nrow0 * kN);
            #pragma unroll
            for (int k = 0; k < 3; ++k) {
                const int idx = t + 512 * k;
                if (idx < nchunks)
                    prefetch_l2(nb + (size_t)idx * 128);
            }
        }

        #pragma unroll
        for (int q = 0; q < NQ; ++q) {
            float4* B = buf + q * kN;
            float4 v[8];
            #pragma unroll
            for (int m = 0; m < 8; ++m) v[m] = B[off[m]];

            substages(v, tw1);

            #pragma unroll
            for (int m = 0; m < 8; ++m) B[off[m]] = v[m];
        }
    }

    // ---- HOISTED: phase-2 twiddle loads before the barrier.
    const int b2 = t >> 6, c2 = t & 63;                   // s = 64
    float4 tw2[3][4];
    #pragma unroll
    for (int u = 0; u < 3; ++u)
        #pragma unroll
        for (int pm = 0; pm < 4; ++pm)
            tw2[u][pm] = tw4[(6 + u) * 2048 + 64 * (4 * b2 + pm) + c2];

    __syncthreads();

    // ------------- Phase 2: stages 6..8 (strides 64,128,256), smem --------
    {
        int off[8];
        #pragma unroll
        for (int m = 0; m < 8; ++m) off[m] = swz(b2 * 512 + c2 + 64 * m);

        #pragma unroll
        for (int q = 0; q < NQ; ++q) {
            float4* B = buf + q * kN;
            float4 v[8];
            #pragma unroll
            for (int m = 0; m < 8; ++m) v[m] = B[off[m]];

            substages(v, tw2);

            #pragma unroll
            for (int m = 0; m < 8; ++m) B[off[m]] = v[m];
        }
    }

    // ---- HOISTED: phase-3 twiddle loads before the barrier.
    float4 tw3[3][4];
    #pragma unroll
    for (int u = 0; u < 3; ++u)
        #pragma unroll
        for (int pm = 0; pm < 4; ++pm)
            tw3[u][pm] = tw4[(9 + u) * 2048 + 512 * pm + t];

    __syncthreads();

    // ------------- Phase 3: stages 9..11 (strides 512..2048) -> out -------
    {
        const int s = 512;  // b = 0, c = t
        int off[8];
        #pragma unroll
        for (int m = 0; m < 8; ++m) off[m] = swz(t + s * m);

        #pragma unroll
        for (int q = 0; q < NQ; ++q) {
            float4* B = buf + q * kN;
            float4 v[8];
            #pragma unroll
            for (int m = 0; m < 8; ++m) v[m] = B[off[m]];

            substages(v, tw3);

            float* o0 = out + (size_t)(row0 + 4 * q) * kN;
            float* o1 = o0 + kN;
            float* o2 = o1 + kN;
            float* o3 = o2 + kN;
            #pragma unroll
            for (int m = 0; m < 8; ++m) {
                __stcs(o0 + t + s * m, v[m].x);   // write-once: streaming
                __stcs(o1 + t + s * m, v[m].y);
                __stcs(o2 + t + s * m, v[m].z);
                __stcs(o3 + t + s * m, v[m].w);
            }
        }
    }
    __syncthreads();   // slots reused by next tile's phase 0
}

__global__ void __launch_bounds__(kThreads, 1)
butterfly_kernel(const float* __restrict__ x,
                 const float* __restrict__ tw,
                 float* __restrict__ out) {
    extern __shared__ float4 buf[];

    for (int tile = blockIdx.x; tile < kTiles; tile += kGrid) {
        const int row0  = tile_row0(tile);
        const int nt    = tile + kGrid;
        const int nrow0 = (nt < kTiles) ? tile_row0(nt) : -1;
        const int nchk  = (nt < kTiles) ? tile_rows(nt) * (kN * 4 / 128) : 0;

        if (tile < kTiles12) {
            bf_body<3>(x, tw, out, row0, nrow0, nchk, buf);   // 12-row tile
        } else {
            bf_body<2>(x, tw, out, row0, nrow0, nchk, buf);   // 8-row tile
        }
    }
}

extern "C" void kernel_launch(void* const* d_in, const int* in_sizes, int n_in,
                              void* d_out, int out_size) {
    const float* x  = (const float*)d_in[0];   // (8192, 4096) fp32
    const float* tw = (const float*)d_in[1];   // (1,1,12,2048,2,2) fp32
    float* out      = (float*)d_out;           // (8192, 4096) fp32

    cudaFuncSetAttribute(butterfly_kernel,
                         cudaFuncAttributeMaxDynamicSharedMemorySize, kSmem);
    butterfly_kernel<<<kGrid, kThreads, kSmem>>>(x, tw, out);
}